// round 15
// baseline (speedup 1.0000x reference)
#include <cuda_runtime.h>
#include <cuda_fp16.h>
#include <cstdint>
#include <cstddef>

// ----------------------------------------------------------------------------
// DiT block: B=1024, S=64, D=768, HID=3072, 12 heads x 64 hd
// Round 15: R14 + staging issued after first MMA block (hide cp.async issue
// behind tensor drain) + merged transpose kernel.
// ----------------------------------------------------------------------------

#define Bq    1024
#define Sq    64
#define Dq    768
#define HIDq  3072
#define NHq   12
#define HDq   64
#define BSq   (Bq * Sq)
#define MODW  (6 * Dq)

// ---------------- scratch -----------------------------------------------------
__device__ __half g_mishc[(size_t)Bq * Dq];
__device__ float  g_mod  [(size_t)Bq * MODW];
__device__ __half g_h    [(size_t)BSq * Dq];
__device__ __half g_qkv  [(size_t)BSq * 3 * Dq];
__device__ __half g_attn [(size_t)BSq * Dq];
__device__ float  g_x2   [(size_t)BSq * Dq];
__device__ __half g_ffn  [(size_t)BSq * HIDq];
// transposed weights [N, K] fp16
#define WT_QKV_OFF 0
#define WT_OUT_OFF (WT_QKV_OFF + 2304 * 768)
#define WT_F1_OFF  (WT_OUT_OFF + 768 * 768)
#define WT_F2_OFF  (WT_F1_OFF  + 3072 * 768)
#define WT_MOD_OFF (WT_F2_OFF  + 768 * 3072)
#define WT_TOTAL   (WT_MOD_OFF + 4608 * 768)
__device__ __half g_wt[(size_t)WT_TOTAL];

// ---------------- helpers -----------------------------------------------------
__device__ __forceinline__ uint32_t smem_u32(const void* p) {
    uint32_t a;
    asm("{ .reg .u64 t; cvta.to.shared.u64 t, %1; cvt.u32.u64 %0, t; }" : "=r"(a) : "l"(p));
    return a;
}
// mish(v) = v * tanh(softplus(v)); tanh(log1p(w)) = (w^2+2w)/(w^2+2w+2), w=e^v
__device__ __forceinline__ float mishf(float v) {
    if (v > 15.0f) return v;
    float w = __expf(v);
    float t = w * (w + 2.0f);
    return v * __fdividef(t, t + 2.0f);
}
__device__ __forceinline__ void ldsm4(uint32_t addr, uint32_t r[4]) {
    asm volatile("ldmatrix.sync.aligned.m8n8.x4.shared.b16 {%0,%1,%2,%3}, [%4];"
        : "=r"(r[0]), "=r"(r[1]), "=r"(r[2]), "=r"(r[3]) : "r"(addr));
}
__device__ __forceinline__ void ldsm4t(uint32_t addr, uint32_t r[4]) {
    asm volatile("ldmatrix.sync.aligned.m8n8.x4.trans.shared.b16 {%0,%1,%2,%3}, [%4];"
        : "=r"(r[0]), "=r"(r[1]), "=r"(r[2]), "=r"(r[3]) : "r"(addr));
}
__device__ __forceinline__ void mma16816(float d[4], const uint32_t a[4], const uint32_t b[2]) {
    asm volatile(
        "mma.sync.aligned.m16n8k16.row.col.f32.f16.f16.f32 "
        "{%0,%1,%2,%3}, {%4,%5,%6,%7}, {%8,%9}, {%0,%1,%2,%3};"
        : "+f"(d[0]), "+f"(d[1]), "+f"(d[2]), "+f"(d[3])
        : "r"(a[0]), "r"(a[1]), "r"(a[2]), "r"(a[3]), "r"(b[0]), "r"(b[1]));
}
__device__ __forceinline__ uint32_t packh2(float x, float y) {
    __half2 h = __floats2half2_rn(x, y);
    return *(uint32_t*)&h;
}
__device__ __forceinline__ void store2(float* p, float v0, float v1) {
    *(float2*)p = make_float2(v0, v1);
}
__device__ __forceinline__ void store2(__half* p, float v0, float v1) {
    *(__half2*)p = __floats2half2_rn(v0, v1);
}

__global__ void mish_kernel(const float* __restrict__ in, __half* __restrict__ outp, int n) {
    int i = blockIdx.x * blockDim.x + threadIdx.x;
    if (i < n) outp[i] = __float2half(mishf(in[i]));
}

// ---------------- merged weight transpose ([K,N] fp32 -> [N,K] fp16) ----------
// segments (32x32 tiles): qkv 72x24 | out 24x24 | f1 96x24 | f2 24x96 | mod 144x24
#define TT_QKV 1728
#define TT_OUT (TT_QKV + 576)
#define TT_F1  (TT_OUT + 2304)
#define TT_F2  (TT_F1 + 2304)
#define TT_ALL (TT_F2 + 3456)
__global__ __launch_bounds__(256)
void transpose_all(const float* __restrict__ Wqkv, const float* __restrict__ Wout,
                   const float* __restrict__ Wf1,  const float* __restrict__ Wf2,
                   const float* __restrict__ Wmod, __half* __restrict__ wt) {
    __shared__ float t[32][33];
    int bid = blockIdx.x;
    const float* W;
    __half* Wt;
    int K, N, ti;
    if (bid < TT_QKV)      { W = Wqkv; Wt = wt + WT_QKV_OFF; K = 768;  N = 2304; ti = bid; }
    else if (bid < TT_OUT) { W = Wout; Wt = wt + WT_OUT_OFF; K = 768;  N = 768;  ti = bid - TT_QKV; }
    else if (bid < TT_F1)  { W = Wf1;  Wt = wt + WT_F1_OFF;  K = 768;  N = 3072; ti = bid - TT_OUT; }
    else if (bid < TT_F2)  { W = Wf2;  Wt = wt + WT_F2_OFF;  K = 3072; N = 768;  ti = bid - TT_F1; }
    else                   { W = Wmod; Wt = wt + WT_MOD_OFF; K = 768;  N = 4608; ti = bid - TT_F2; }
    int nt = N / 32;
    int n0 = (ti % nt) * 32, k0 = (ti / nt) * 32;
    int x = threadIdx.x, y = threadIdx.y;
    #pragma unroll
    for (int i = 0; i < 32; i += 8) t[y + i][x] = W[(size_t)(k0 + y + i) * N + n0 + x];
    __syncthreads();
    #pragma unroll
    for (int i = 0; i < 32; i += 8)
        Wt[(size_t)(n0 + y + i) * K + k0 + x] = __float2half(t[x][y + i]);
}

// ---------------- LayerNorm + modulation (fp32 in, fp16 out) ------------------
__global__ __launch_bounds__(256)
void ln_mod_kernel(const float* __restrict__ X, const float* __restrict__ mod,
                   __half* __restrict__ Y, int shiftOff, int scaleOff) {
    __shared__ float red [8];
    __shared__ float red2[8];
    __shared__ float stats[2];
    int t   = blockIdx.x;
    int tid = threadIdx.x;
    const float* xr = X + (size_t)t * Dq;
    float v0 = xr[tid], v1 = xr[tid + 256], v2 = xr[tid + 512];
    float s  = v0 + v1 + v2;
    float sq = v0 * v0 + v1 * v1 + v2 * v2;
    #pragma unroll
    for (int o = 16; o > 0; o >>= 1) {
        s  += __shfl_xor_sync(0xffffffffu, s,  o);
        sq += __shfl_xor_sync(0xffffffffu, sq, o);
    }
    int w = tid >> 5, lane = tid & 31;
    if (lane == 0) { red[w] = s; red2[w] = sq; }
    __syncthreads();
    if (tid == 0) {
        float S = 0.f, SQ = 0.f;
        #pragma unroll
        for (int i = 0; i < 8; i++) { S += red[i]; SQ += red2[i]; }
        float mean = S * (1.0f / Dq);
        float var  = SQ * (1.0f / Dq) - mean * mean;
        stats[0] = mean;
        stats[1] = rsqrtf(var + 1e-5f);
    }
    __syncthreads();
    float mean = stats[0], r = stats[1];
    const float* mrow = mod + (size_t)(t >> 6) * MODW;
    __half* yr = Y + (size_t)t * Dq;
    yr[tid]       = __float2half((v0 - mean) * r * (1.0f + mrow[scaleOff + tid])       + mrow[shiftOff + tid]);
    yr[tid + 256] = __float2half((v1 - mean) * r * (1.0f + mrow[scaleOff + tid + 256]) + mrow[shiftOff + tid + 256]);
    yr[tid + 512] = __float2half((v2 - mean) * r * (1.0f + mrow[scaleOff + tid + 512]) + mrow[shiftOff + tid + 512]);
}

// ---------------- fp16 mma.sync GEMM ------------------------------------------
// C[M,N] = epi(A[M,K] @ Bt[N,K]^T + bias),  A/Bt fp16, accum fp32.
// EPI 0: +bias   EPI 1: mish(+bias)   EPI 2: resid + gate*(+bias)
#define TILE_M 128
#define TILE_N 128
#define TILE_K 64
#define STAGE_BYTES 32768
#define SMEM_GEMM (3 * STAGE_BYTES)

__device__ __forceinline__ void stage_tile(const __half* __restrict__ g, int ldg,
                                           uint32_t dstBase, int tid) {
    #pragma unroll
    for (int i = 0; i < 8; i++) {
        int idx = tid + i * 128;
        int row = idx >> 3, q = idx & 7;
        uint32_t dst = dstBase + row * 128 + ((q ^ (row & 7)) << 4);
        const __half* src = g + (size_t)row * ldg + q * 8;
        asm volatile("cp.async.cg.shared.global [%0], [%1], 16;" :: "r"(dst), "l"(src));
    }
}

__device__ __forceinline__ void ldfrag(uint32_t aSm, uint32_t bSm, int ks,
                                       const uint32_t rowA[4], const uint32_t rowB[4],
                                       int qA, int qB, int l7,
                                       uint32_t a[4][4], uint32_t b[8][2]) {
    const uint32_t xa = (uint32_t)(((2 * ks + qA) ^ l7) << 4);
    const uint32_t xb = (uint32_t)(((2 * ks + qB) ^ l7) << 4);
    #pragma unroll
    for (int mi = 0; mi < 4; mi++)
        ldsm4(aSm + rowA[mi] + xa, a[mi]);
    #pragma unroll
    for (int p = 0; p < 4; p++) {
        uint32_t t[4];
        ldsm4(bSm + rowB[p] + xb, t);
        b[2 * p    ][0] = t[0];
        b[2 * p    ][1] = t[1];
        b[2 * p + 1][0] = t[2];
        b[2 * p + 1][1] = t[3];
    }
}

template <int EPI, typename OutT>
__global__ __launch_bounds__(128, 2)
void gemm_mma(const __half* __restrict__ A, const __half* __restrict__ Bt,
              const float* __restrict__ bias, OutT* __restrict__ C,
              int M, int N, int K,
              const float* __restrict__ mod, int modOff,
              const float* __restrict__ resid) {
    extern __shared__ char smem[];
    const uint32_t sb = smem_u32(smem);
    const int tid  = threadIdx.x;
    const int lane = tid & 31;
    const int warp = tid >> 5;
    const int grp  = lane >> 2;
    const int tig  = lane & 3;
    const int warpM = warp >> 1;
    const int warpN = warp & 1;
    const int mBase = blockIdx.y * TILE_M;
    const int nBase = blockIdx.x * TILE_N;

    const int l7  = lane & 7;
    const int l15 = lane & 15;
    const int qA  = lane >> 4;
    const int qB  = (lane >> 3) & 1;
    uint32_t rowA[4], rowB[4];
    #pragma unroll
    for (int mi = 0; mi < 4; mi++)
        rowA[mi] = (uint32_t)((warpM * 64 + mi * 16 + l15) * 128);
    #pragma unroll
    for (int p = 0; p < 4; p++)
        rowB[p] = (uint32_t)((warpN * 64 + p * 16 + ((lane >> 4) & 1) * 8 + l7) * 128);

    float d[4][8][4];
    #pragma unroll
    for (int mi = 0; mi < 4; mi++)
        #pragma unroll
        for (int nj = 0; nj < 8; nj++)
            #pragma unroll
            for (int r = 0; r < 4; r++) d[mi][nj][r] = 0.f;

    const __half* Abase = A  + (size_t)mBase * K;
    const __half* Bbase = Bt + (size_t)nBase * K;
    const int NC = K / TILE_K;

    stage_tile(Abase, K, sb, tid);
    stage_tile(Bbase, K, sb + 16384, tid);
    asm volatile("cp.async.commit_group;");
    stage_tile(Abase + TILE_K, K, sb + STAGE_BYTES, tid);
    stage_tile(Bbase + TILE_K, K, sb + STAGE_BYTES + 16384, tid);
    asm volatile("cp.async.commit_group;");

    int st = 0;
    for (int c = 0; c < NC; c++) {
        if (c + 2 < NC) asm volatile("cp.async.wait_group 1;");
        else            asm volatile("cp.async.wait_group 0;");
        __syncthreads();

        const uint32_t aSm = sb + st * STAGE_BYTES;
        const uint32_t bSm = aSm + 16384;

        uint32_t af[2][4][4], bf[2][8][2];
        // load fragments for ks=0 and ks=1 first
        ldfrag(aSm, bSm, 0, rowA, rowB, qA, qB, l7, af[0], bf[0]);
        ldfrag(aSm, bSm, 1, rowA, rowB, qA, qB, l7, af[1], bf[1]);

        // ks = 0 MMAs start the tensor pipe
        #pragma unroll
        for (int nj = 0; nj < 8; nj++)
            #pragma unroll
            for (int mi = 0; mi < 4; mi++)
                mma16816(d[mi][nj], af[0][mi], bf[0][nj]);

        // stage chunk c+2 while the tensor pipe drains ks=0
        if (c + 2 < NC) {
            int s2 = st + 2; if (s2 >= 3) s2 -= 3;
            uint32_t dst = sb + s2 * STAGE_BYTES;
            stage_tile(Abase + (c + 2) * TILE_K, K, dst, tid);
            stage_tile(Bbase + (c + 2) * TILE_K, K, dst + 16384, tid);
            asm volatile("cp.async.commit_group;");
        }

        #pragma unroll
        for (int ks = 1; ks < 4; ks++) {
            if (ks < 3)
                ldfrag(aSm, bSm, ks + 1, rowA, rowB, qA, qB, l7,
                       af[(ks + 1) & 1], bf[(ks + 1) & 1]);
            const int cur = ks & 1;
            #pragma unroll
            for (int nj = 0; nj < 8; nj++)
                #pragma unroll
                for (int mi = 0; mi < 4; mi++)
                    mma16816(d[mi][nj], af[cur][mi], bf[cur][nj]);
        }
        st++; if (st >= 3) st = 0;
    }

    // ---------------- epilogue ------------------------------------------------
    const int m0 = mBase + warpM * 64;
    const int n0 = nBase + warpN * 64;
    const float* modrow = (EPI == 2) ? (mod + (size_t)(m0 >> 6) * MODW + modOff) : nullptr;

    #pragma unroll
    for (int nj = 0; nj < 8; nj++) {
        int n = n0 + nj * 8 + tig * 2;
        float bv0 = __ldg(bias + n);
        float bv1 = __ldg(bias + n + 1);
        float g0 = 0.f, g1 = 0.f;
        if (EPI == 2) { g0 = modrow[n]; g1 = modrow[n + 1]; }
        #pragma unroll
        for (int mi = 0; mi < 4; mi++) {
            int m = m0 + mi * 16 + grp;
            #pragma unroll
            for (int hh = 0; hh < 2; hh++) {
                int mm = m + hh * 8;
                float v0 = d[mi][nj][hh * 2 + 0] + bv0;
                float v1 = d[mi][nj][hh * 2 + 1] + bv1;
                if (EPI == 1) {
                    v0 = mishf(v0);
                    v1 = mishf(v1);
                } else if (EPI == 2) {
                    const float2 rr = *(const float2*)(resid + (size_t)mm * N + n);
                    v0 = rr.x + g0 * v0;
                    v1 = rr.y + g1 * v1;
                }
                store2(C + (size_t)mm * N + n, v0, v1);
            }
        }
    }
}

// ---------------- tensor-core attention ----------------------------------------
__global__ __launch_bounds__(128)
void attn_mma(const __half* __restrict__ QKV, __half* __restrict__ O) {
    __shared__ __align__(128) char sm[3 * 8192];
    const uint32_t sb = smem_u32(sm);
    const int tid  = threadIdx.x;
    const int lane = tid & 31;
    const int w    = tid >> 5;
    const int grp  = lane >> 2;
    const int tig  = lane & 3;
    const int l7   = lane & 7;
    const int h    = blockIdx.x;
    const int b    = blockIdx.y;
    const size_t base = (size_t)b * 64 * (3 * Dq) + (size_t)h * HDq;

    #pragma unroll
    for (int m = 0; m < 3; m++) {
        #pragma unroll
        for (int i = 0; i < 4; i++) {
            int idx = tid + i * 128;
            int row = idx >> 3, q = idx & 7;
            uint32_t dst = sb + m * 8192 + row * 128 + ((q ^ (row & 7)) << 4);
            const __half* src = QKV + base + (size_t)m * Dq + (size_t)row * (3 * Dq) + q * 8;
            asm volatile("cp.async.cg.shared.global [%0], [%1], 16;" :: "r"(dst), "l"(src));
        }
    }
    asm volatile("cp.async.commit_group;");
    asm volatile("cp.async.wait_group 0;");
    __syncthreads();

    const uint32_t qb = sb, kb = sb + 8192, vb = sb + 16384;
    const uint32_t rowQ = (uint32_t)((w * 16 + (lane & 15)) * 128);
    uint32_t rowK[4];
    #pragma unroll
    for (int p = 0; p < 4; p++)
        rowK[p] = (uint32_t)((p * 16 + ((lane >> 4) & 1) * 8 + l7) * 128);
    const int qselA = lane >> 4;
    const int qselB = (lane >> 3) & 1;
    const uint32_t rowVbase = (uint32_t)((((lane >> 3) & 1) * 8 + l7) * 128);
    const int qselV = lane >> 4;

    float c[8][4];
    #pragma unroll
    for (int j = 0; j < 8; j++)
        #pragma unroll
        for (int r = 0; r < 4; r++) c[j][r] = 0.f;

    #pragma unroll
    for (int ks = 0; ks < 4; ks++) {
        uint32_t aq[4];
        ldsm4(qb + rowQ + (uint32_t)(((2 * ks + qselA) ^ l7) << 4), aq);
        uint32_t bk[8][2];
        #pragma unroll
        for (int p = 0; p < 4; p++) {
            uint32_t t[4];
            ldsm4(kb + rowK[p] + (uint32_t)(((2 * ks + qselB) ^ l7) << 4), t);
            bk[2 * p][0] = t[0]; bk[2 * p][1] = t[1];
            bk[2 * p + 1][0] = t[2]; bk[2 * p + 1][1] = t[3];
        }
        #pragma unroll
        for (int j = 0; j < 8; j++)
            mma16816(c[j], aq, bk[j]);
    }

    float mx0 = -1e30f, mx1 = -1e30f;
    #pragma unroll
    for (int j = 0; j < 8; j++) {
        #pragma unroll
        for (int r = 0; r < 4; r++) c[j][r] *= 0.125f;
        mx0 = fmaxf(mx0, fmaxf(c[j][0], c[j][1]));
        mx1 = fmaxf(mx1, fmaxf(c[j][2], c[j][3]));
    }
    mx0 = fmaxf(mx0, __shfl_xor_sync(0xffffffffu, mx0, 1));
    mx0 = fmaxf(mx0, __shfl_xor_sync(0xffffffffu, mx0, 2));
    mx1 = fmaxf(mx1, __shfl_xor_sync(0xffffffffu, mx1, 1));
    mx1 = fmaxf(mx1, __shfl_xor_sync(0xffffffffu, mx1, 2));
    float s0 = 0.f, s1 = 0.f;
    #pragma unroll
    for (int j = 0; j < 8; j++) {
        c[j][0] = __expf(c[j][0] - mx0);
        c[j][1] = __expf(c[j][1] - mx0);
        c[j][2] = __expf(c[j][2] - mx1);
        c[j][3] = __expf(c[j][3] - mx1);
        s0 += c[j][0] + c[j][1];
        s1 += c[j][2] + c[j][3];
    }
    s0 += __shfl_xor_sync(0xffffffffu, s0, 1);
    s0 += __shfl_xor_sync(0xffffffffu, s0, 2);
    s1 += __shfl_xor_sync(0xffffffffu, s1, 1);
    s1 += __shfl_xor_sync(0xffffffffu, s1, 2);
    const float r0 = 1.0f / s0, r1 = 1.0f / s1;
    #pragma unroll
    for (int j = 0; j < 8; j++) {
        c[j][0] *= r0; c[j][1] *= r0;
        c[j][2] *= r1; c[j][3] *= r1;
    }

    float o[8][4];
    #pragma unroll
    for (int j = 0; j < 8; j++)
        #pragma unroll
        for (int r = 0; r < 4; r++) o[j][r] = 0.f;

    #pragma unroll
    for (int ks = 0; ks < 4; ks++) {
        uint32_t ap[4];
        ap[0] = packh2(c[2 * ks][0],     c[2 * ks][1]);
        ap[1] = packh2(c[2 * ks][2],     c[2 * ks][3]);
        ap[2] = packh2(c[2 * ks + 1][0], c[2 * ks + 1][1]);
        ap[3] = packh2(c[2 * ks + 1][2], c[2 * ks + 1][3]);
        uint32_t bv[8][2];
        #pragma unroll
        for (int p = 0; p < 4; p++) {
            uint32_t t[4];
            ldsm4t(vb + (uint32_t)(16 * ks * 128) + rowVbase +
                   (uint32_t)((((2 * p + qselV) ^ l7)) << 4), t);
            bv[2 * p][0] = t[0]; bv[2 * p][1] = t[1];
            bv[2 * p + 1][0] = t[2]; bv[2 * p + 1][1] = t[3];
        }
        #pragma unroll
        for (int j = 0; j < 8; j++)
            mma16816(o[j], ap, bv[j]);
    }

    const int tok = b * 64 + w * 16 + grp;
    __half* orow = O + (size_t)tok * Dq + h * HDq;
    #pragma unroll
    for (int j = 0; j < 8; j++) {
        int col = 8 * j + 2 * tig;
        store2(orow + col, o[j][0], o[j][1]);
        store2(orow + 8 * Dq + col, o[j][2], o[j][3]);
    }
}

// ---------------- launch ------------------------------------------------------
extern "C" void kernel_launch(void* const* d_in, const int* in_sizes, int n_in,
                              void* d_out, int out_size) {
    const float* x     = (const float*)d_in[0];
    const float* c     = (const float*)d_in[1];
    const float* W_mod = (const float*)d_in[2];
    const float* b_mod = (const float*)d_in[3];
    const float* W_qkv = (const float*)d_in[4];
    const float* b_qkv = (const float*)d_in[5];
    const float* W_out = (const float*)d_in[6];
    const float* b_out = (const float*)d_in[7];
    const float* W_f1  = (const float*)d_in[8];
    const float* b_f1  = (const float*)d_in[9];
    const float* W_f2  = (const float*)d_in[10];
    const float* b_f2  = (const float*)d_in[11];
    float* out = (float*)d_out;

    __half *mishc, *hbuf, *qkv, *attn, *ffn, *wt;
    float *modp, *x2;
    cudaGetSymbolAddress((void**)&mishc, g_mishc);
    cudaGetSymbolAddress((void**)&modp,  g_mod);
    cudaGetSymbolAddress((void**)&hbuf,  g_h);
    cudaGetSymbolAddress((void**)&qkv,   g_qkv);
    cudaGetSymbolAddress((void**)&attn,  g_attn);
    cudaGetSymbolAddress((void**)&x2,    g_x2);
    cudaGetSymbolAddress((void**)&ffn,   g_ffn);
    cudaGetSymbolAddress((void**)&wt,    g_wt);

    cudaFuncSetAttribute(gemm_mma<0, float>,  cudaFuncAttributeMaxDynamicSharedMemorySize, SMEM_GEMM);
    cudaFuncSetAttribute(gemm_mma<0, __half>, cudaFuncAttributeMaxDynamicSharedMemorySize, SMEM_GEMM);
    cudaFuncSetAttribute(gemm_mma<1, __half>, cudaFuncAttributeMaxDynamicSharedMemorySize, SMEM_GEMM);
    cudaFuncSetAttribute(gemm_mma<2, float>,  cudaFuncAttributeMaxDynamicSharedMemorySize, SMEM_GEMM);

    // merged weight transposes ([K,N] fp32 -> [N,K] fp16)
    transpose_all<<<TT_ALL, dim3(32, 8)>>>(W_qkv, W_out, W_f1, W_f2, W_mod, wt);

    // 1) mish(c) -> fp16
    mish_kernel<<<(Bq * Dq + 255) / 256, 256>>>(c, mishc, Bq * Dq);
    // 2) mod = mish(c) @ W_mod + b_mod        (fp32 out)
    gemm_mma<0, float><<<dim3(MODW / TILE_N, Bq / TILE_M), 128, SMEM_GEMM>>>(
        mishc, wt + WT_MOD_OFF, b_mod, modp, Bq, MODW, Dq, nullptr, 0, nullptr);
    // 3) h1 = LN(x)*(1+scale1)+shift1         (fp16 out)
    ln_mod_kernel<<<BSq, 256>>>(x, modp, hbuf, 0, Dq);
    // 4) qkv = h1 @ W_qkv + b_qkv             (fp16 out)
    gemm_mma<0, __half><<<dim3(3 * Dq / TILE_N, BSq / TILE_M), 128, SMEM_GEMM>>>(
        hbuf, wt + WT_QKV_OFF, b_qkv, qkv, BSq, 3 * Dq, Dq, nullptr, 0, nullptr);
    // 5) attention (tensor cores)
    attn_mma<<<dim3(NHq, Bq), 128>>>(qkv, attn);
    // 6) x2 = x + gate1 * (attn @ W_out + b_out)   (fp32 out)
    gemm_mma<2, float><<<dim3(Dq / TILE_N, BSq / TILE_M), 128, SMEM_GEMM>>>(
        attn, wt + WT_OUT_OFF, b_out, x2, BSq, Dq, Dq, modp, 2 * Dq, x);
    // 7) h2 = LN(x2)*(1+scale2)+shift2        (fp16 out)
    ln_mod_kernel<<<BSq, 256>>>(x2, modp, hbuf, 3 * Dq, 4 * Dq);
    // 8) ffn = mish(h2 @ W_f1 + b_f1)         (fp16 out)
    gemm_mma<1, __half><<<dim3(HIDq / TILE_N, BSq / TILE_M), 128, SMEM_GEMM>>>(
        hbuf, wt + WT_F1_OFF, b_f1, ffn, BSq, HIDq, Dq, nullptr, 0, nullptr);
    // 9) out = x2 + gate2 * (ffn @ W_f2 + b_f2)    (fp32 out)
    gemm_mma<2, float><<<dim3(Dq / TILE_N, BSq / TILE_M), 128, SMEM_GEMM>>>(
        ffn, wt + WT_F2_OFF, b_f2, out, BSq, Dq, HIDq, modp, 5 * Dq, x2);
}

// round 17
// speedup vs baseline: 1.0265x; 1.0265x over previous
#include <cuda_runtime.h>
#include <cuda_fp16.h>
#include <cstdint>
#include <cstddef>

// ----------------------------------------------------------------------------
// DiT block: B=1024, S=64, D=768, HID=3072, 12 heads x 64 hd
// Round 16: R15 + vectorized 4-row ln_mod kernel (float4 loads, 1 barrier).
// GEMMs at legacy-HMMA ceiling (~400 TF/s); attacking the non-GEMM tail.
// ----------------------------------------------------------------------------

#define Bq    1024
#define Sq    64
#define Dq    768
#define HIDq  3072
#define NHq   12
#define HDq   64
#define BSq   (Bq * Sq)
#define MODW  (6 * Dq)

// ---------------- scratch -----------------------------------------------------
__device__ __half g_mishc[(size_t)Bq * Dq];
__device__ float  g_mod  [(size_t)Bq * MODW];
__device__ __half g_h    [(size_t)BSq * Dq];
__device__ __half g_qkv  [(size_t)BSq * 3 * Dq];
__device__ __half g_attn [(size_t)BSq * Dq];
__device__ float  g_x2   [(size_t)BSq * Dq];
__device__ __half g_ffn  [(size_t)BSq * HIDq];
// transposed weights [N, K] fp16
#define WT_QKV_OFF 0
#define WT_OUT_OFF (WT_QKV_OFF + 2304 * 768)
#define WT_F1_OFF  (WT_OUT_OFF + 768 * 768)
#define WT_F2_OFF  (WT_F1_OFF  + 3072 * 768)
#define WT_MOD_OFF (WT_F2_OFF  + 768 * 3072)
#define WT_TOTAL   (WT_MOD_OFF + 4608 * 768)
__device__ __half g_wt[(size_t)WT_TOTAL];

// ---------------- helpers -----------------------------------------------------
__device__ __forceinline__ uint32_t smem_u32(const void* p) {
    uint32_t a;
    asm("{ .reg .u64 t; cvta.to.shared.u64 t, %1; cvt.u32.u64 %0, t; }" : "=r"(a) : "l"(p));
    return a;
}
// mish(v) = v * tanh(softplus(v)); tanh(log1p(w)) = (w^2+2w)/(w^2+2w+2), w=e^v
__device__ __forceinline__ float mishf(float v) {
    if (v > 15.0f) return v;
    float w = __expf(v);
    float t = w * (w + 2.0f);
    return v * __fdividef(t, t + 2.0f);
}
__device__ __forceinline__ void ldsm4(uint32_t addr, uint32_t r[4]) {
    asm volatile("ldmatrix.sync.aligned.m8n8.x4.shared.b16 {%0,%1,%2,%3}, [%4];"
        : "=r"(r[0]), "=r"(r[1]), "=r"(r[2]), "=r"(r[3]) : "r"(addr));
}
__device__ __forceinline__ void ldsm4t(uint32_t addr, uint32_t r[4]) {
    asm volatile("ldmatrix.sync.aligned.m8n8.x4.trans.shared.b16 {%0,%1,%2,%3}, [%4];"
        : "=r"(r[0]), "=r"(r[1]), "=r"(r[2]), "=r"(r[3]) : "r"(addr));
}
__device__ __forceinline__ void mma16816(float d[4], const uint32_t a[4], const uint32_t b[2]) {
    asm volatile(
        "mma.sync.aligned.m16n8k16.row.col.f32.f16.f16.f32 "
        "{%0,%1,%2,%3}, {%4,%5,%6,%7}, {%8,%9}, {%0,%1,%2,%3};"
        : "+f"(d[0]), "+f"(d[1]), "+f"(d[2]), "+f"(d[3])
        : "r"(a[0]), "r"(a[1]), "r"(a[2]), "r"(a[3]), "r"(b[0]), "r"(b[1]));
}
__device__ __forceinline__ uint32_t packh2(float x, float y) {
    __half2 h = __floats2half2_rn(x, y);
    return *(uint32_t*)&h;
}
__device__ __forceinline__ void store2(float* p, float v0, float v1) {
    *(float2*)p = make_float2(v0, v1);
}
__device__ __forceinline__ void store2(__half* p, float v0, float v1) {
    *(__half2*)p = __floats2half2_rn(v0, v1);
}

__global__ void mish_kernel(const float* __restrict__ in, __half* __restrict__ outp, int n) {
    int i = blockIdx.x * blockDim.x + threadIdx.x;
    if (i < n) outp[i] = __float2half(mishf(in[i]));
}

// ---------------- merged weight transpose ([K,N] fp32 -> [N,K] fp16) ----------
#define TT_QKV 1728
#define TT_OUT (TT_QKV + 576)
#define TT_F1  (TT_OUT + 2304)
#define TT_F2  (TT_F1 + 2304)
#define TT_ALL (TT_F2 + 3456)
__global__ __launch_bounds__(256)
void transpose_all(const float* __restrict__ Wqkv, const float* __restrict__ Wout,
                   const float* __restrict__ Wf1,  const float* __restrict__ Wf2,
                   const float* __restrict__ Wmod, __half* __restrict__ wt) {
    __shared__ float t[32][33];
    int bid = blockIdx.x;
    const float* W;
    __half* Wt;
    int K, N, ti;
    if (bid < TT_QKV)      { W = Wqkv; Wt = wt + WT_QKV_OFF; K = 768;  N = 2304; ti = bid; }
    else if (bid < TT_OUT) { W = Wout; Wt = wt + WT_OUT_OFF; K = 768;  N = 768;  ti = bid - TT_QKV; }
    else if (bid < TT_F1)  { W = Wf1;  Wt = wt + WT_F1_OFF;  K = 768;  N = 3072; ti = bid - TT_OUT; }
    else if (bid < TT_F2)  { W = Wf2;  Wt = wt + WT_F2_OFF;  K = 3072; N = 768;  ti = bid - TT_F1; }
    else                   { W = Wmod; Wt = wt + WT_MOD_OFF; K = 768;  N = 4608; ti = bid - TT_F2; }
    int nt = N / 32;
    int n0 = (ti % nt) * 32, k0 = (ti / nt) * 32;
    int x = threadIdx.x, y = threadIdx.y;
    #pragma unroll
    for (int i = 0; i < 32; i += 8) t[y + i][x] = W[(size_t)(k0 + y + i) * N + n0 + x];
    __syncthreads();
    #pragma unroll
    for (int i = 0; i < 32; i += 8)
        Wt[(size_t)(n0 + y + i) * K + k0 + x] = __float2half(t[x][y + i]);
}

// ---------------- LayerNorm + modulation (vectorized, 4 rows/CTA) -------------
// Y[t,:] = LN(X[t,:]) * (1 + mod[b, scaleOff+:]) + mod[b, shiftOff+:]   (fp16 out)
__global__ __launch_bounds__(256)
void ln_mod_kernel(const float* __restrict__ X, const float* __restrict__ mod,
                   __half* __restrict__ Y, int shiftOff, int scaleOff) {
    __shared__ float red[8][2];
    const int tid  = threadIdx.x;
    const int w    = tid >> 5;
    const int lane = tid & 31;
    const int r    = tid >> 6;      // row within block (0..3)
    const int j    = tid & 63;      // float4 index within row (0..63; row has 192)
    const int t    = blockIdx.x * 4 + r;

    const float4* xr = (const float4*)(X + (size_t)t * Dq);
    float4 a = xr[j], b = xr[j + 64], c4 = xr[j + 128];

    float s  = a.x + a.y + a.z + a.w + b.x + b.y + b.z + b.w + c4.x + c4.y + c4.z + c4.w;
    float sq = a.x*a.x + a.y*a.y + a.z*a.z + a.w*a.w
             + b.x*b.x + b.y*b.y + b.z*b.z + b.w*b.w
             + c4.x*c4.x + c4.y*c4.y + c4.z*c4.z + c4.w*c4.w;
    #pragma unroll
    for (int o = 16; o > 0; o >>= 1) {
        s  += __shfl_xor_sync(0xffffffffu, s,  o);
        sq += __shfl_xor_sync(0xffffffffu, sq, o);
    }
    if (lane == 0) { red[w][0] = s; red[w][1] = sq; }
    __syncthreads();
    const float S    = red[2 * r][0] + red[2 * r + 1][0];
    const float SQ   = red[2 * r][1] + red[2 * r + 1][1];
    const float mean = S * (1.0f / Dq);
    const float var  = SQ * (1.0f / Dq) - mean * mean;
    const float rstd = rsqrtf(var + 1e-5f);

    const float* mrow = mod + (size_t)(t >> 6) * MODW;
    const float4* msc = (const float4*)(mrow + scaleOff);
    const float4* msh = (const float4*)(mrow + shiftOff);
    __half* yr = Y + (size_t)t * Dq;

    #pragma unroll
    for (int ch = 0; ch < 3; ch++) {
        const int jj = j + ch * 64;
        const float4 v  = (ch == 0) ? a : (ch == 1) ? b : c4;
        const float4 sc = msc[jj];
        const float4 sh = msh[jj];
        __half2 h0 = __floats2half2_rn((v.x - mean) * rstd * (1.0f + sc.x) + sh.x,
                                       (v.y - mean) * rstd * (1.0f + sc.y) + sh.y);
        __half2 h1 = __floats2half2_rn((v.z - mean) * rstd * (1.0f + sc.z) + sh.z,
                                       (v.w - mean) * rstd * (1.0f + sc.w) + sh.w);
        uint2 pk;
        pk.x = *(uint32_t*)&h0;
        pk.y = *(uint32_t*)&h1;
        *(uint2*)(yr + jj * 4) = pk;
    }
}

// ---------------- fp16 mma.sync GEMM ------------------------------------------
// C[M,N] = epi(A[M,K] @ Bt[N,K]^T + bias),  A/Bt fp16, accum fp32.
// EPI 0: +bias   EPI 1: mish(+bias)   EPI 2: resid + gate*(+bias)
#define TILE_M 128
#define TILE_N 128
#define TILE_K 64
#define STAGE_BYTES 32768
#define SMEM_GEMM (3 * STAGE_BYTES)

__device__ __forceinline__ void stage_tile(const __half* __restrict__ g, int ldg,
                                           uint32_t dstBase, int tid) {
    #pragma unroll
    for (int i = 0; i < 8; i++) {
        int idx = tid + i * 128;
        int row = idx >> 3, q = idx & 7;
        uint32_t dst = dstBase + row * 128 + ((q ^ (row & 7)) << 4);
        const __half* src = g + (size_t)row * ldg + q * 8;
        asm volatile("cp.async.cg.shared.global [%0], [%1], 16;" :: "r"(dst), "l"(src));
    }
}

__device__ __forceinline__ void ldfrag(uint32_t aSm, uint32_t bSm, int ks,
                                       const uint32_t rowA[4], const uint32_t rowB[4],
                                       int qA, int qB, int l7,
                                       uint32_t a[4][4], uint32_t b[8][2]) {
    const uint32_t xa = (uint32_t)(((2 * ks + qA) ^ l7) << 4);
    const uint32_t xb = (uint32_t)(((2 * ks + qB) ^ l7) << 4);
    #pragma unroll
    for (int mi = 0; mi < 4; mi++)
        ldsm4(aSm + rowA[mi] + xa, a[mi]);
    #pragma unroll
    for (int p = 0; p < 4; p++) {
        uint32_t t[4];
        ldsm4(bSm + rowB[p] + xb, t);
        b[2 * p    ][0] = t[0];
        b[2 * p    ][1] = t[1];
        b[2 * p + 1][0] = t[2];
        b[2 * p + 1][1] = t[3];
    }
}

template <int EPI, typename OutT>
__global__ __launch_bounds__(128, 2)
void gemm_mma(const __half* __restrict__ A, const __half* __restrict__ Bt,
              const float* __restrict__ bias, OutT* __restrict__ C,
              int M, int N, int K,
              const float* __restrict__ mod, int modOff,
              const float* __restrict__ resid) {
    extern __shared__ char smem[];
    const uint32_t sb = smem_u32(smem);
    const int tid  = threadIdx.x;
    const int lane = tid & 31;
    const int warp = tid >> 5;
    const int grp  = lane >> 2;
    const int tig  = lane & 3;
    const int warpM = warp >> 1;
    const int warpN = warp & 1;
    const int mBase = blockIdx.y * TILE_M;
    const int nBase = blockIdx.x * TILE_N;

    const int l7  = lane & 7;
    const int l15 = lane & 15;
    const int qA  = lane >> 4;
    const int qB  = (lane >> 3) & 1;
    uint32_t rowA[4], rowB[4];
    #pragma unroll
    for (int mi = 0; mi < 4; mi++)
        rowA[mi] = (uint32_t)((warpM * 64 + mi * 16 + l15) * 128);
    #pragma unroll
    for (int p = 0; p < 4; p++)
        rowB[p] = (uint32_t)((warpN * 64 + p * 16 + ((lane >> 4) & 1) * 8 + l7) * 128);

    float d[4][8][4];
    #pragma unroll
    for (int mi = 0; mi < 4; mi++)
        #pragma unroll
        for (int nj = 0; nj < 8; nj++)
            #pragma unroll
            for (int r = 0; r < 4; r++) d[mi][nj][r] = 0.f;

    const __half* Abase = A  + (size_t)mBase * K;
    const __half* Bbase = Bt + (size_t)nBase * K;
    const int NC = K / TILE_K;

    stage_tile(Abase, K, sb, tid);
    stage_tile(Bbase, K, sb + 16384, tid);
    asm volatile("cp.async.commit_group;");
    stage_tile(Abase + TILE_K, K, sb + STAGE_BYTES, tid);
    stage_tile(Bbase + TILE_K, K, sb + STAGE_BYTES + 16384, tid);
    asm volatile("cp.async.commit_group;");

    int st = 0;
    for (int c = 0; c < NC; c++) {
        if (c + 2 < NC) asm volatile("cp.async.wait_group 1;");
        else            asm volatile("cp.async.wait_group 0;");
        __syncthreads();

        const uint32_t aSm = sb + st * STAGE_BYTES;
        const uint32_t bSm = aSm + 16384;

        uint32_t af[2][4][4], bf[2][8][2];
        ldfrag(aSm, bSm, 0, rowA, rowB, qA, qB, l7, af[0], bf[0]);
        ldfrag(aSm, bSm, 1, rowA, rowB, qA, qB, l7, af[1], bf[1]);

        #pragma unroll
        for (int nj = 0; nj < 8; nj++)
            #pragma unroll
            for (int mi = 0; mi < 4; mi++)
                mma16816(d[mi][nj], af[0][mi], bf[0][nj]);

        if (c + 2 < NC) {
            int s2 = st + 2; if (s2 >= 3) s2 -= 3;
            uint32_t dst = sb + s2 * STAGE_BYTES;
            stage_tile(Abase + (c + 2) * TILE_K, K, dst, tid);
            stage_tile(Bbase + (c + 2) * TILE_K, K, dst + 16384, tid);
            asm volatile("cp.async.commit_group;");
        }

        #pragma unroll
        for (int ks = 1; ks < 4; ks++) {
            if (ks < 3)
                ldfrag(aSm, bSm, ks + 1, rowA, rowB, qA, qB, l7,
                       af[(ks + 1) & 1], bf[(ks + 1) & 1]);
            const int cur = ks & 1;
            #pragma unroll
            for (int nj = 0; nj < 8; nj++)
                #pragma unroll
                for (int mi = 0; mi < 4; mi++)
                    mma16816(d[mi][nj], af[cur][mi], bf[cur][nj]);
        }
        st++; if (st >= 3) st = 0;
    }

    // ---------------- epilogue ------------------------------------------------
    const int m0 = mBase + warpM * 64;
    const int n0 = nBase + warpN * 64;
    const float* modrow = (EPI == 2) ? (mod + (size_t)(m0 >> 6) * MODW + modOff) : nullptr;

    #pragma unroll
    for (int nj = 0; nj < 8; nj++) {
        int n = n0 + nj * 8 + tig * 2;
        float bv0 = __ldg(bias + n);
        float bv1 = __ldg(bias + n + 1);
        float g0 = 0.f, g1 = 0.f;
        if (EPI == 2) { g0 = modrow[n]; g1 = modrow[n + 1]; }
        #pragma unroll
        for (int mi = 0; mi < 4; mi++) {
            int m = m0 + mi * 16 + grp;
            #pragma unroll
            for (int hh = 0; hh < 2; hh++) {
                int mm = m + hh * 8;
                float v0 = d[mi][nj][hh * 2 + 0] + bv0;
                float v1 = d[mi][nj][hh * 2 + 1] + bv1;
                if (EPI == 1) {
                    v0 = mishf(v0);
                    v1 = mishf(v1);
                } else if (EPI == 2) {
                    const float2 rr = *(const float2*)(resid + (size_t)mm * N + n);
                    v0 = rr.x + g0 * v0;
                    v1 = rr.y + g1 * v1;
                }
                store2(C + (size_t)mm * N + n, v0, v1);
            }
        }
    }
}

// ---------------- tensor-core attention ----------------------------------------
__global__ __launch_bounds__(128)
void attn_mma(const __half* __restrict__ QKV, __half* __restrict__ O) {
    __shared__ __align__(128) char sm[3 * 8192];
    const uint32_t sb = smem_u32(sm);
    const int tid  = threadIdx.x;
    const int lane = tid & 31;
    const int w    = tid >> 5;
    const int grp  = lane >> 2;
    const int tig  = lane & 3;
    const int l7   = lane & 7;
    const int h    = blockIdx.x;
    const int b    = blockIdx.y;
    const size_t base = (size_t)b * 64 * (3 * Dq) + (size_t)h * HDq;

    #pragma unroll
    for (int m = 0; m < 3; m++) {
        #pragma unroll
        for (int i = 0; i < 4; i++) {
            int idx = tid + i * 128;
            int row = idx >> 3, q = idx & 7;
            uint32_t dst = sb + m * 8192 + row * 128 + ((q ^ (row & 7)) << 4);
            const __half* src = QKV + base + (size_t)m * Dq + (size_t)row * (3 * Dq) + q * 8;
            asm volatile("cp.async.cg.shared.global [%0], [%1], 16;" :: "r"(dst), "l"(src));
        }
    }
    asm volatile("cp.async.commit_group;");
    asm volatile("cp.async.wait_group 0;");
    __syncthreads();

    const uint32_t qb = sb, kb = sb + 8192, vb = sb + 16384;
    const uint32_t rowQ = (uint32_t)((w * 16 + (lane & 15)) * 128);
    uint32_t rowK[4];
    #pragma unroll
    for (int p = 0; p < 4; p++)
        rowK[p] = (uint32_t)((p * 16 + ((lane >> 4) & 1) * 8 + l7) * 128);
    const int qselA = lane >> 4;
    const int qselB = (lane >> 3) & 1;
    const uint32_t rowVbase = (uint32_t)((((lane >> 3) & 1) * 8 + l7) * 128);
    const int qselV = lane >> 4;

    float c[8][4];
    #pragma unroll
    for (int j = 0; j < 8; j++)
        #pragma unroll
        for (int r = 0; r < 4; r++) c[j][r] = 0.f;

    #pragma unroll
    for (int ks = 0; ks < 4; ks++) {
        uint32_t aq[4];
        ldsm4(qb + rowQ + (uint32_t)(((2 * ks + qselA) ^ l7) << 4), aq);
        uint32_t bk[8][2];
        #pragma unroll
        for (int p = 0; p < 4; p++) {
            uint32_t t[4];
            ldsm4(kb + rowK[p] + (uint32_t)(((2 * ks + qselB) ^ l7) << 4), t);
            bk[2 * p][0] = t[0]; bk[2 * p][1] = t[1];
            bk[2 * p + 1][0] = t[2]; bk[2 * p + 1][1] = t[3];
        }
        #pragma unroll
        for (int j = 0; j < 8; j++)
            mma16816(c[j], aq, bk[j]);
    }

    float mx0 = -1e30f, mx1 = -1e30f;
    #pragma unroll
    for (int j = 0; j < 8; j++) {
        #pragma unroll
        for (int r = 0; r < 4; r++) c[j][r] *= 0.125f;
        mx0 = fmaxf(mx0, fmaxf(c[j][0], c[j][1]));
        mx1 = fmaxf(mx1, fmaxf(c[j][2], c[j][3]));
    }
    mx0 = fmaxf(mx0, __shfl_xor_sync(0xffffffffu, mx0, 1));
    mx0 = fmaxf(mx0, __shfl_xor_sync(0xffffffffu, mx0, 2));
    mx1 = fmaxf(mx1, __shfl_xor_sync(0xffffffffu, mx1, 1));
    mx1 = fmaxf(mx1, __shfl_xor_sync(0xffffffffu, mx1, 2));
    float s0 = 0.f, s1 = 0.f;
    #pragma unroll
    for (int j = 0; j < 8; j++) {
        c[j][0] = __expf(c[j][0] - mx0);
        c[j][1] = __expf(c[j][1] - mx0);
        c[j][2] = __expf(c[j][2] - mx1);
        c[j][3] = __expf(c[j][3] - mx1);
        s0 += c[j][0] + c[j][1];
        s1 += c[j][2] + c[j][3];
    }
    s0 += __shfl_xor_sync(0xffffffffu, s0, 1);
    s0 += __shfl_xor_sync(0xffffffffu, s0, 2);
    s1 += __shfl_xor_sync(0xffffffffu, s1, 1);
    s1 += __shfl_xor_sync(0xffffffffu, s1, 2);
    const float r0 = 1.0f / s0, r1 = 1.0f / s1;
    #pragma unroll
    for (int j = 0; j < 8; j++) {
        c[j][0] *= r0; c[j][1] *= r0;
        c[j][2] *= r1; c[j][3] *= r1;
    }

    float o[8][4];
    #pragma unroll
    for (int j = 0; j < 8; j++)
        #pragma unroll
        for (int r = 0; r < 4; r++) o[j][r] = 0.f;

    #pragma unroll
    for (int ks = 0; ks < 4; ks++) {
        uint32_t ap[4];
        ap[0] = packh2(c[2 * ks][0],     c[2 * ks][1]);
        ap[1] = packh2(c[2 * ks][2],     c[2 * ks][3]);
        ap[2] = packh2(c[2 * ks + 1][0], c[2 * ks + 1][1]);
        ap[3] = packh2(c[2 * ks + 1][2], c[2 * ks + 1][3]);
        uint32_t bv[8][2];
        #pragma unroll
        for (int p = 0; p < 4; p++) {
            uint32_t t[4];
            ldsm4t(vb + (uint32_t)(16 * ks * 128) + rowVbase +
                   (uint32_t)((((2 * p + qselV) ^ l7)) << 4), t);
            bv[2 * p][0] = t[0]; bv[2 * p][1] = t[1];
            bv[2 * p + 1][0] = t[2]; bv[2 * p + 1][1] = t[3];
        }
        #pragma unroll
        for (int j = 0; j < 8; j++)
            mma16816(o[j], ap, bv[j]);
    }

    const int tok = b * 64 + w * 16 + grp;
    __half* orow = O + (size_t)tok * Dq + h * HDq;
    #pragma unroll
    for (int j = 0; j < 8; j++) {
        int col = 8 * j + 2 * tig;
        store2(orow + col, o[j][0], o[j][1]);
        store2(orow + 8 * Dq + col, o[j][2], o[j][3]);
    }
}

// ---------------- launch ------------------------------------------------------
extern "C" void kernel_launch(void* const* d_in, const int* in_sizes, int n_in,
                              void* d_out, int out_size) {
    const float* x     = (const float*)d_in[0];
    const float* c     = (const float*)d_in[1];
    const float* W_mod = (const float*)d_in[2];
    const float* b_mod = (const float*)d_in[3];
    const float* W_qkv = (const float*)d_in[4];
    const float* b_qkv = (const float*)d_in[5];
    const float* W_out = (const float*)d_in[6];
    const float* b_out = (const float*)d_in[7];
    const float* W_f1  = (const float*)d_in[8];
    const float* b_f1  = (const float*)d_in[9];
    const float* W_f2  = (const float*)d_in[10];
    const float* b_f2  = (const float*)d_in[11];
    float* out = (float*)d_out;

    __half *mishc, *hbuf, *qkv, *attn, *ffn, *wt;
    float *modp, *x2;
    cudaGetSymbolAddress((void**)&mishc, g_mishc);
    cudaGetSymbolAddress((void**)&modp,  g_mod);
    cudaGetSymbolAddress((void**)&hbuf,  g_h);
    cudaGetSymbolAddress((void**)&qkv,   g_qkv);
    cudaGetSymbolAddress((void**)&attn,  g_attn);
    cudaGetSymbolAddress((void**)&x2,    g_x2);
    cudaGetSymbolAddress((void**)&ffn,   g_ffn);
    cudaGetSymbolAddress((void**)&wt,    g_wt);

    cudaFuncSetAttribute(gemm_mma<0, float>,  cudaFuncAttributeMaxDynamicSharedMemorySize, SMEM_GEMM);
    cudaFuncSetAttribute(gemm_mma<0, __half>, cudaFuncAttributeMaxDynamicSharedMemorySize, SMEM_GEMM);
    cudaFuncSetAttribute(gemm_mma<1, __half>, cudaFuncAttributeMaxDynamicSharedMemorySize, SMEM_GEMM);
    cudaFuncSetAttribute(gemm_mma<2, float>,  cudaFuncAttributeMaxDynamicSharedMemorySize, SMEM_GEMM);

    // merged weight transposes ([K,N] fp32 -> [N,K] fp16)
    transpose_all<<<TT_ALL, dim3(32, 8)>>>(W_qkv, W_out, W_f1, W_f2, W_mod, wt);

    // 1) mish(c) -> fp16
    mish_kernel<<<(Bq * Dq + 255) / 256, 256>>>(c, mishc, Bq * Dq);
    // 2) mod = mish(c) @ W_mod + b_mod        (fp32 out)
    gemm_mma<0, float><<<dim3(MODW / TILE_N, Bq / TILE_M), 128, SMEM_GEMM>>>(
        mishc, wt + WT_MOD_OFF, b_mod, modp, Bq, MODW, Dq, nullptr, 0, nullptr);
    // 3) h1 = LN(x)*(1+scale1)+shift1         (fp16 out)
    ln_mod_kernel<<<BSq / 4, 256>>>(x, modp, hbuf, 0, Dq);
    // 4) qkv = h1 @ W_qkv + b_qkv             (fp16 out)
    gemm_mma<0, __half><<<dim3(3 * Dq / TILE_N, BSq / TILE_M), 128, SMEM_GEMM>>>(
        hbuf, wt + WT_QKV_OFF, b_qkv, qkv, BSq, 3 * Dq, Dq, nullptr, 0, nullptr);
    // 5) attention (tensor cores)
    attn_mma<<<dim3(NHq, Bq), 128>>>(qkv, attn);
    // 6) x2 = x + gate1 * (attn @ W_out + b_out)   (fp32 out)
    gemm_mma<2, float><<<dim3(Dq / TILE_N, BSq / TILE_M), 128, SMEM_GEMM>>>(
        attn, wt + WT_OUT_OFF, b_out, x2, BSq, Dq, Dq, modp, 2 * Dq, x);
    // 7) h2 = LN(x2)*(1+scale2)+shift2        (fp16 out)
    ln_mod_kernel<<<BSq / 4, 256>>>(x2, modp, hbuf, 3 * Dq, 4 * Dq);
    // 8) ffn = mish(h2 @ W_f1 + b_f1)         (fp16 out)
    gemm_mma<1, __half><<<dim3(HIDq / TILE_N, BSq / TILE_M), 128, SMEM_GEMM>>>(
        hbuf, wt + WT_F1_OFF, b_f1, ffn, BSq, HIDq, Dq, nullptr, 0, nullptr);
    // 9) out = x2 + gate2 * (ffn @ W_f2 + b_f2)    (fp32 out)
    gemm_mma<2, float><<<dim3(Dq / TILE_N, BSq / TILE_M), 128, SMEM_GEMM>>>(
        ffn, wt + WT_F2_OFF, b_f2, out, BSq, Dq, HIDq, modp, 5 * Dq, x2);
}